// round 9
// baseline (speedup 1.0000x reference)
#include <cuda_runtime.h>

// CRPS loss, fused single kernel — R9: maximize independent warp streams.
//   term1 = mean_i |s_i - y|
//   term2 = 0.5 * mean_{i,j} |s_i - s_j| = (1/256) * sum_k (2k-15) * s_(k)  (sorted)
// result = mean over pixels of (term1 - term2)
//
// All previous rounds (half2-packed, 2-4 px/thread) were pinned at 8.3-9.4us
// with issue=15%: dependency-latency bound in the sort network with only
// ~4096 independent warp chains. This round: 1 px/thread, pure fp32
// (no F2FP conversions), 262144 threads = 8192 warps = 2x the independent
// chains, occ ~80%. Scalar FMNMX sort, FFMA-imm weighted sum.

#define NS          16
#define TOTAL_PIX   (4 * 1 * 256 * 256)   // B*C*H*W = 262144
#define NBLOCKS     1024
#define NTHREADS    256

__device__ float g_part[NBLOCKS];
__device__ unsigned int g_count = 0;   // zero-initialized at module load

// compare-exchange (ascending) on scalar float
#define CE(i, j)                                   \
    {                                              \
        float _lo = fminf(v[i], v[j]);             \
        v[j] = fmaxf(v[i], v[j]);                  \
        v[i] = _lo;                                \
    }

// Batcher odd-even mergesort network for 16 elements (63 compare-exchanges)
__device__ __forceinline__ void sort16(float v[16]) {
    CE(0,1)  CE(2,3)  CE(4,5)   CE(6,7)   CE(8,9)   CE(10,11) CE(12,13) CE(14,15)
    CE(0,2)  CE(1,3)  CE(4,6)   CE(5,7)   CE(8,10)  CE(9,11)  CE(12,14) CE(13,15)
    CE(1,2)  CE(5,6)  CE(9,10)  CE(13,14)
    CE(0,4)  CE(1,5)  CE(2,6)   CE(3,7)   CE(8,12)  CE(9,13)  CE(10,14) CE(11,15)
    CE(2,4)  CE(3,5)  CE(10,12) CE(11,13)
    CE(1,2)  CE(3,4)  CE(5,6)   CE(9,10)  CE(11,12) CE(13,14)
    CE(0,8)  CE(1,9)  CE(2,10)  CE(3,11)  CE(4,12)  CE(5,13)  CE(6,14)  CE(7,15)
    CE(4,8)  CE(5,9)  CE(6,10)  CE(7,11)
    CE(2,4)  CE(3,5)  CE(6,8)   CE(7,9)   CE(10,12) CE(11,13)
    CE(1,2)  CE(3,4)  CE(5,6)   CE(7,8)   CE(9,10)  CE(11,12) CE(13,14)
}

__global__ void __launch_bounds__(NTHREADS, 6)
crps_kernel(const float* __restrict__ samples, const float* __restrict__ target,
            float* __restrict__ out) {
    int g = blockIdx.x * NTHREADS + threadIdx.x;   // pixel index, 0..262143

    // ── front-batched loads: 16 independent coalesced LDG.32 ──
    float v[16];
#pragma unroll
    for (int n = 0; n < 16; n++)
        v[n] = samples[n * TOTAL_PIX + g];
    float y = target[g];

    // term1 raw sum: sum_i |s_i - y|
    float s1 = 0.0f;
#pragma unroll
    for (int n = 0; n < 16; n++)
        s1 += fabsf(v[n] - y);

    sort16(v);

    // weighted sum over sorted values: sum_k (2k-15) * s_(k)  (FFMA-imm chain)
    float sw = 0.0f;
#pragma unroll
    for (int k = 0; k < 16; k++)
        sw = fmaf(v[k], (float)(2 * k - 15), sw);

    // per-pixel CRPS contribution
    float val = s1 * (1.0f / 16.0f) - sw * (1.0f / 256.0f);

    // ── deterministic block reduction ──
#pragma unroll
    for (int o = 16; o > 0; o >>= 1)
        val += __shfl_xor_sync(0xffffffffu, val, o);

    __shared__ float sm[NTHREADS / 32];
    __shared__ int is_last;
    int lane = threadIdx.x & 31;
    int warp = threadIdx.x >> 5;
    if (lane == 0) sm[warp] = val;
    __syncthreads();
    if (warp == 0) {
        float v2 = (lane < (NTHREADS / 32)) ? sm[lane] : 0.0f;
#pragma unroll
        for (int o = 4; o > 0; o >>= 1)
            v2 += __shfl_xor_sync(0xffffffffu, v2, o);
        if (lane == 0) {
            g_part[blockIdx.x] = v2;
            __threadfence();
            unsigned int old = atomicAdd(&g_count, 1u);
            is_last = (old == NBLOCKS - 1) ? 1 : 0;
        }
    }
    __syncthreads();

    // ── last block: final reduction over 1024 partials (fixed order) ──
    if (is_last) {
        const float4* p4 = (const float4*)g_part;     // 256 float4
        float4 a = p4[threadIdx.x];
        float v2 = a.x + a.y + a.z + a.w;
#pragma unroll
        for (int o = 16; o > 0; o >>= 1)
            v2 += __shfl_xor_sync(0xffffffffu, v2, o);
        if (lane == 0) sm[warp] = v2;
        __syncthreads();
        if (threadIdx.x == 0) {
            float tot = 0.0f;
#pragma unroll
            for (int w = 0; w < NTHREADS / 32; w++)
                tot += sm[w];
            out[0] = tot * (1.0f / (float)TOTAL_PIX);
            g_count = 0;              // reset for next graph replay
        }
    }
}

extern "C" void kernel_launch(void* const* d_in, const int* in_sizes, int n_in,
                              void* d_out, int out_size) {
    const float* samples = (const float*)d_in[0];
    const float* target  = (const float*)d_in[1];
    // defensive: pick by element count (samples = 16x larger)
    if (n_in >= 2 && in_sizes[0] < in_sizes[1]) {
        const float* t = samples; samples = target; target = t;
    }
    crps_kernel<<<NBLOCKS, NTHREADS>>>(samples, target, (float*)d_out);
}